// round 2
// baseline (speedup 1.0000x reference)
#include <cuda_runtime.h>
#include <math.h>

#define NN 100000
#define EE 1600000
#define FIN 128
#define HD  64
#define CC  40
#define LL  6

// ---------------- scratch (static device allocation; no cudaMalloc) ----------------
__device__ int   g_deg[NN];
__device__ int   g_rowptr[NN + 1];
__device__ int   g_fill[NN];
__device__ float g_dis[NN];
__device__ int   g_colidx[EE];
__device__ float g_bufA[(size_t)NN * HD];   // ping: dis-scaled pre-aggregation features
__device__ float g_bufB[(size_t)NN * HD];   // pong
__device__ float g_jk[(size_t)NN * HD];     // running JumpingKnowledge max

// ---------------- graph preprocessing ----------------
__global__ void k_zero_deg() {
    int i = blockIdx.x * blockDim.x + threadIdx.x;
    if (i < NN) g_deg[i] = 0;
}

__global__ void k_count(const int* __restrict__ dst) {
    int e = blockIdx.x * blockDim.x + threadIdx.x;
    if (e < EE) atomicAdd(&g_deg[dst[e]], 1);
}

// Single-block exclusive scan: thread-sequential segments + block scan of 1024 partials.
__global__ void k_scan() {
    __shared__ int sh[1024];
    int tid = threadIdx.x;
    const int SEG = (NN + 1023) / 1024;   // 98
    int beg = tid * SEG;
    int end = min(beg + SEG, NN);
    int s = 0;
    for (int i = beg; i < end; i++) s += g_deg[i];
    sh[tid] = s;
    __syncthreads();
    for (int off = 1; off < 1024; off <<= 1) {
        int t = (tid >= off) ? sh[tid - off] : 0;
        __syncthreads();
        sh[tid] += t;
        __syncthreads();
    }
    int run = sh[tid] - s;                 // exclusive prefix for this segment
    for (int i = beg; i < end; i++) { g_rowptr[i] = run; run += g_deg[i]; }
    if (tid == 1023) g_rowptr[NN] = sh[1023];   // == EE
}

__global__ void k_init() {
    int i = blockIdx.x * blockDim.x + threadIdx.x;
    if (i < NN) {
        g_fill[i] = g_rowptr[i];
        g_dis[i] = rsqrtf((float)(g_deg[i] + 1));   // +1: self loop
    }
}

__global__ void k_scatter(const int* __restrict__ src, const int* __restrict__ dst) {
    int e = blockIdx.x * blockDim.x + threadIdx.x;
    if (e < EE) {
        int p = atomicAdd(&g_fill[dst[e]], 1);
        g_colidx[p] = src[e];
    }
}

// ---------------- layer-0 GEMM:  hn[row,:] = dis[row] * (x[row,:] @ W0)  ----------------
__global__ void k_gemm0(const float* __restrict__ A, const float* __restrict__ W,
                        float* __restrict__ out) {
    __shared__ float As[64][68];
    __shared__ float Bs[64][68];
    int tid = threadIdx.x;
    int tx = tid & 15, ty = tid >> 4;
    int brow = blockIdx.x * 64;
    float acc[4][4] = {};

    for (int kc = 0; kc < FIN; kc += 64) {
        int c4 = tx * 4;
        #pragma unroll
        for (int i = 0; i < 4; i++) {
            int r = ty + 16 * i;
            int row = brow + r;
            float4 v = make_float4(0.f, 0.f, 0.f, 0.f);
            if (row < NN) v = *(const float4*)&A[(size_t)row * FIN + kc + c4];
            *(float4*)&As[r][c4] = v;
        }
        #pragma unroll
        for (int i = 0; i < 4; i++) {
            int kr = ty + 16 * i;
            *(float4*)&Bs[kr][c4] = *(const float4*)&W[(size_t)(kc + kr) * HD + c4];
        }
        __syncthreads();

        #pragma unroll
        for (int k = 0; k < 64; k++) {
            float a0 = As[ty * 4 + 0][k];
            float a1 = As[ty * 4 + 1][k];
            float a2 = As[ty * 4 + 2][k];
            float a3 = As[ty * 4 + 3][k];
            float4 b = *(float4*)&Bs[k][tx * 4];
            acc[0][0] += a0 * b.x; acc[0][1] += a0 * b.y; acc[0][2] += a0 * b.z; acc[0][3] += a0 * b.w;
            acc[1][0] += a1 * b.x; acc[1][1] += a1 * b.y; acc[1][2] += a1 * b.z; acc[1][3] += a1 * b.w;
            acc[2][0] += a2 * b.x; acc[2][1] += a2 * b.y; acc[2][2] += a2 * b.z; acc[2][3] += a2 * b.w;
            acc[3][0] += a3 * b.x; acc[3][1] += a3 * b.y; acc[3][2] += a3 * b.z; acc[3][3] += a3 * b.w;
        }
        __syncthreads();
    }

    #pragma unroll
    for (int i = 0; i < 4; i++) {
        int row = brow + ty * 4 + i;
        if (row < NN) {
            float d = g_dis[row];
            float4 o = make_float4(acc[i][0] * d, acc[i][1] * d, acc[i][2] * d, acc[i][3] * d);
            *(float4*)&out[(size_t)row * HD + tx * 4] = o;
        }
    }
}

// ---------------- fused aggregation + next-layer GEMM ----------------
// Per warp (node v):
//   h[v,:] = relu(dis[v]*(hn_in[v,:] + sum_{u->v} hn_in[u,:]) + b)
//   jk     = first ? h : max(jk, h)
//   hn_out[v,:] = dis[v] * (h[v,:] @ Wnext)       (skipped in last layer)
__device__ __forceinline__ void warp_agg(const float* __restrict__ hn_in,
                                         const float* __restrict__ bias,
                                         int v, int lane, int first,
                                         float& hx, float& hy, float& d, size_t& fo) {
    int beg = g_rowptr[v], end = g_rowptr[v + 1];
    fo = (size_t)v * HD + lane * 2;
    float2 acc = *(const float2*)&hn_in[fo];   // self-loop term

    for (int base = beg; base < end; base += 32) {
        int m = end - base; if (m > 32) m = 32;
        int u = 0;
        if (lane < m) u = g_colidx[base + lane];
        int i = 0;
        for (; i + 4 <= m; i += 4) {
            int u0 = __shfl_sync(0xffffffffu, u, i + 0);
            int u1 = __shfl_sync(0xffffffffu, u, i + 1);
            int u2 = __shfl_sync(0xffffffffu, u, i + 2);
            int u3 = __shfl_sync(0xffffffffu, u, i + 3);
            float2 t0 = *(const float2*)&hn_in[(size_t)u0 * HD + lane * 2];
            float2 t1 = *(const float2*)&hn_in[(size_t)u1 * HD + lane * 2];
            float2 t2 = *(const float2*)&hn_in[(size_t)u2 * HD + lane * 2];
            float2 t3 = *(const float2*)&hn_in[(size_t)u3 * HD + lane * 2];
            acc.x += (t0.x + t1.x) + (t2.x + t3.x);
            acc.y += (t0.y + t1.y) + (t2.y + t3.y);
        }
        for (; i < m; i++) {
            int ui = __shfl_sync(0xffffffffu, u, i);
            float2 t = *(const float2*)&hn_in[(size_t)ui * HD + lane * 2];
            acc.x += t.x; acc.y += t.y;
        }
    }

    d = g_dis[v];
    float2 b = *(const float2*)&bias[lane * 2];
    hx = fmaxf(fmaf(d, acc.x, b.x), 0.f);
    hy = fmaxf(fmaf(d, acc.y, b.y), 0.f);

    if (first) {
        *(float2*)&g_jk[fo] = make_float2(hx, hy);
    } else {
        float2 j = *(const float2*)&g_jk[fo];
        *(float2*)&g_jk[fo] = make_float2(fmaxf(j.x, hx), fmaxf(j.y, hy));
    }
}

__global__ void k_agg_fused(const float* __restrict__ hn_in, float* __restrict__ hn_out,
                            const float* __restrict__ W, const float* __restrict__ bias,
                            int first) {
    __shared__ float4 Wp[32][32];   // Wp[kk][c2] = {W[2kk][2c2],W[2kk][2c2+1],W[2kk+1][2c2],W[2kk+1][2c2+1]}
    int tid = threadIdx.x;
    #pragma unroll
    for (int e = 0; e < 4; e++) {
        int idx = tid + e * 256;          // 1024 float4 entries
        int kk = idx >> 5, ln = idx & 31;
        float2 a = *(const float2*)&W[(size_t)(2 * kk)     * HD + 2 * ln];
        float2 b = *(const float2*)&W[(size_t)(2 * kk + 1) * HD + 2 * ln];
        Wp[kk][ln] = make_float4(a.x, a.y, b.x, b.y);
    }
    __syncthreads();

    int warp = (blockIdx.x * blockDim.x + tid) >> 5;
    int lane = tid & 31;
    if (warp >= NN) return;

    float hx, hy, d; size_t fo;
    warp_agg(hn_in, bias, warp, lane, first, hx, hy, d, fo);

    // in-warp GEMM: o[c] = sum_k h[k] * W[k][c], c = {2*lane, 2*lane+1}
    float2 o = make_float2(0.f, 0.f);
    #pragma unroll
    for (int kk = 0; kk < 32; kk++) {
        float ax = __shfl_sync(0xffffffffu, hx, kk);   // h[2kk]
        float ay = __shfl_sync(0xffffffffu, hy, kk);   // h[2kk+1]
        float4 w = Wp[kk][lane];
        o.x = fmaf(ax, w.x, o.x); o.y = fmaf(ax, w.y, o.y);
        o.x = fmaf(ay, w.z, o.x); o.y = fmaf(ay, w.w, o.y);
    }
    *(float2*)&hn_out[fo] = make_float2(d * o.x, d * o.y);
}

__global__ void k_agg_last(const float* __restrict__ hn_in, const float* __restrict__ bias,
                           int first) {
    int warp = (blockIdx.x * blockDim.x + threadIdx.x) >> 5;
    int lane = threadIdx.x & 31;
    if (warp >= NN) return;
    float hx, hy, d; size_t fo;
    warp_agg(hn_in, bias, warp, lane, first, hx, hy, d, fo);
    (void)d; (void)fo; (void)hx; (void)hy;   // jk already updated inside warp_agg
}

// ---------------- head: warp per row, jk @ fc_w + fc_b, log_softmax ----------------
__global__ void k_proj(const float* __restrict__ fcw, const float* __restrict__ fcb,
                       float* __restrict__ out) {
    __shared__ float Wsm[HD * CC];
    __shared__ float bsm[CC];
    int tid = threadIdx.x;
    for (int i = tid; i < HD * CC; i += blockDim.x) Wsm[i] = fcw[i];
    if (tid < CC) bsm[tid] = fcb[tid];
    __syncthreads();

    int warp = (blockIdx.x * blockDim.x + tid) >> 5;
    int lane = tid & 31;
    if (warp >= NN) return;
    int v = warp;

    float2 jv = *(const float2*)&g_jk[(size_t)v * HD + lane * 2];
    bool act = lane < 20;                   // 20 lanes x 2 cols = 40
    int c0 = lane * 2;
    float a0 = 0.f, a1 = 0.f;
    #pragma unroll
    for (int k = 0; k < HD; k++) {
        float hv = __shfl_sync(0xffffffffu, (k & 1) ? jv.y : jv.x, k >> 1);
        if (act) {
            float2 w = *(const float2*)&Wsm[k * CC + c0];
            a0 = fmaf(hv, w.x, a0);
            a1 = fmaf(hv, w.y, a1);
        }
    }
    if (act) { a0 += bsm[c0]; a1 += bsm[c0 + 1]; }

    float m = act ? fmaxf(a0, a1) : -INFINITY;
    #pragma unroll
    for (int off = 16; off; off >>= 1) m = fmaxf(m, __shfl_xor_sync(0xffffffffu, m, off));
    float s = act ? (expf(a0 - m) + expf(a1 - m)) : 0.f;
    #pragma unroll
    for (int off = 16; off; off >>= 1) s += __shfl_xor_sync(0xffffffffu, s, off);
    float lse = m + logf(s);

    if (act) {
        float2 o = make_float2(a0 - lse, a1 - lse);
        *(float2*)&out[(size_t)v * CC + c0] = o;
    }
}

// ---------------- launch ----------------
extern "C" void kernel_launch(void* const* d_in, const int* in_sizes, int n_in,
                              void* d_out, int out_size) {
    const float* x   = (const float*)d_in[0];
    const int*   ei  = (const int*)  d_in[1];
    const float* W0  = (const float*)d_in[2];
    const float* Ws  = (const float*)d_in[3];
    const float* bs  = (const float*)d_in[4];
    const float* fcw = (const float*)d_in[5];
    const float* fcb = (const float*)d_in[6];
    float* out = (float*)d_out;

    const int* src = ei;         // edge_index[0]
    const int* dst = ei + EE;    // edge_index[1]

    // CSR build (once per call, reused by all 6 layers)
    k_zero_deg<<<(NN + 255) / 256, 256>>>();
    k_count   <<<(EE + 255) / 256, 256>>>(dst);
    k_scan    <<<1, 1024>>>();
    k_init    <<<(NN + 255) / 256, 256>>>();
    k_scatter <<<(EE + 255) / 256, 256>>>(src, dst);

    const int GEMM_GRID = (NN + 63) / 64;
    const int AGG_GRID  = (NN + 7) / 8;     // 8 warps per 256-thread block

    float* bufA; float* bufB;
    cudaGetSymbolAddress((void**)&bufA, g_bufA);
    cudaGetSymbolAddress((void**)&bufB, g_bufB);

    // layer 0: x (N x 128) @ W0 -> bufA
    k_gemm0<<<GEMM_GRID, 256>>>(x, W0, bufA);

    // layers 0..4 aggregation, each fused with the NEXT layer's GEMM (Ws[l])
    float* cur = bufA; float* nxt = bufB;
    for (int l = 0; l < LL - 1; l++) {
        k_agg_fused<<<AGG_GRID, 256>>>(cur, nxt, Ws + (size_t)l * HD * HD,
                                       bs + (size_t)l * HD, l == 0);
        float* t = cur; cur = nxt; nxt = t;
    }
    // layer 5 aggregation: no next GEMM
    k_agg_last<<<AGG_GRID, 256>>>(cur, bs + (size_t)(LL - 1) * HD, 0);

    // head
    k_proj<<<AGG_GRID, 256>>>(fcw, fcb, out);
}

// round 3
// speedup vs baseline: 1.1427x; 1.1427x over previous
#include <cuda_runtime.h>
#include <math.h>

#define NN 100000
#define EE 1600000
#define FIN 128
#define HD  64
#define CC  40
#define LL  6

// ---------------- scratch (static device allocation; no cudaMalloc) ----------------
__device__ int   g_deg[NN];
__device__ int   g_rowptr[NN + 1];
__device__ int   g_fill[NN];
__device__ float g_dis[NN];
__device__ int   g_colidx[EE];
__device__ float g_hn[(size_t)NN * HD];   // dis-scaled pre-aggregation features
__device__ float g_h [(size_t)NN * HD];   // post-relu layer output (next layer input)
__device__ float g_jk[(size_t)NN * HD];   // running JumpingKnowledge max

// ---------------- graph preprocessing ----------------
__global__ void k_zero_deg() {
    int i = blockIdx.x * blockDim.x + threadIdx.x;
    if (i < NN) g_deg[i] = 0;
}

__global__ void k_count(const int* __restrict__ dst) {
    int e = blockIdx.x * blockDim.x + threadIdx.x;
    if (e < EE) atomicAdd(&g_deg[dst[e]], 1);
}

// Single-block exclusive scan + init (fill, dis) fused.
__global__ void k_scan() {
    __shared__ int sh[1024];
    int tid = threadIdx.x;
    const int SEG = (NN + 1023) / 1024;   // 98
    int beg = tid * SEG;
    int end = min(beg + SEG, NN);
    int s = 0;
    for (int i = beg; i < end; i++) s += g_deg[i];
    sh[tid] = s;
    __syncthreads();
    for (int off = 1; off < 1024; off <<= 1) {
        int t = (tid >= off) ? sh[tid - off] : 0;
        __syncthreads();
        sh[tid] += t;
        __syncthreads();
    }
    int run = sh[tid] - s;                 // exclusive prefix for this segment
    for (int i = beg; i < end; i++) {
        int d = g_deg[i];
        g_rowptr[i] = run;
        g_fill[i]   = run;
        g_dis[i]    = rsqrtf((float)(d + 1));   // +1: self loop
        run += d;
    }
    if (tid == 1023) g_rowptr[NN] = sh[1023];   // == EE
}

__global__ void k_scatter(const int* __restrict__ src, const int* __restrict__ dst) {
    int e = blockIdx.x * blockDim.x + threadIdx.x;
    if (e < EE) {
        int p = atomicAdd(&g_fill[dst[e]], 1);
        g_colidx[p] = src[e];
    }
}

// ---------------- GEMM:  hn[row,:] = dis[row] * (A[row,:] @ W)  ----------------
// 64x64 output tile, K staged in 64-wide chunks, 4x4 microtile per thread (256 thr).
template<int K, bool FROMX>
__global__ void k_gemm(const float* __restrict__ Aext, const float* __restrict__ W) {
    __shared__ float As[64][68];
    __shared__ float Bs[64][68];
    const float* __restrict__ A = FROMX ? Aext : (const float*)g_h;
    int tid = threadIdx.x;
    int tx = tid & 15, ty = tid >> 4;
    int brow = blockIdx.x * 64;
    float acc[4][4] = {};

    for (int kc = 0; kc < K; kc += 64) {
        int c4 = tx * 4;
        #pragma unroll
        for (int i = 0; i < 4; i++) {
            int r = ty + 16 * i;
            int row = brow + r;
            float4 v = make_float4(0.f, 0.f, 0.f, 0.f);
            if (row < NN) v = *(const float4*)&A[(size_t)row * K + kc + c4];
            *(float4*)&As[r][c4] = v;
        }
        #pragma unroll
        for (int i = 0; i < 4; i++) {
            int kr = ty + 16 * i;
            *(float4*)&Bs[kr][c4] = *(const float4*)&W[(size_t)(kc + kr) * HD + c4];
        }
        __syncthreads();

        #pragma unroll
        for (int k = 0; k < 64; k++) {
            float a0 = As[ty * 4 + 0][k];
            float a1 = As[ty * 4 + 1][k];
            float a2 = As[ty * 4 + 2][k];
            float a3 = As[ty * 4 + 3][k];
            float4 b = *(float4*)&Bs[k][tx * 4];
            acc[0][0] += a0 * b.x; acc[0][1] += a0 * b.y; acc[0][2] += a0 * b.z; acc[0][3] += a0 * b.w;
            acc[1][0] += a1 * b.x; acc[1][1] += a1 * b.y; acc[1][2] += a1 * b.z; acc[1][3] += a1 * b.w;
            acc[2][0] += a2 * b.x; acc[2][1] += a2 * b.y; acc[2][2] += a2 * b.z; acc[2][3] += a2 * b.w;
            acc[3][0] += a3 * b.x; acc[3][1] += a3 * b.y; acc[3][2] += a3 * b.z; acc[3][3] += a3 * b.w;
        }
        __syncthreads();
    }

    #pragma unroll
    for (int i = 0; i < 4; i++) {
        int row = brow + ty * 4 + i;
        if (row < NN) {
            float d = g_dis[row];
            float4 o = make_float4(acc[i][0] * d, acc[i][1] * d, acc[i][2] * d, acc[i][3] * d);
            *(float4*)&g_hn[(size_t)row * HD + tx * 4] = o;
        }
    }
}

// ---------------- aggregation: warp per node, CSR pull + self term ----------------
// Uniform-address colidx loads (int4, L1 broadcast) + 8 gathers in flight.
__device__ __forceinline__ float2 warp_gather_sum(int v, int lane) {
    int beg = g_rowptr[v], end = g_rowptr[v + 1];
    size_t fo = (size_t)v * HD + lane * 2;
    float2 acc = *(const float2*)&g_hn[fo];   // self-loop term

    int p = beg;
    // align p to 4 for int4 colidx loads
    while (p < end && (p & 3)) {
        int u = g_colidx[p++];
        float2 t = *(const float2*)&g_hn[(size_t)u * HD + lane * 2];
        acc.x += t.x; acc.y += t.y;
    }
    for (; p + 8 <= end; p += 8) {
        int4 c0 = *(const int4*)&g_colidx[p];
        int4 c1 = *(const int4*)&g_colidx[p + 4];
        float2 t0 = *(const float2*)&g_hn[(size_t)c0.x * HD + lane * 2];
        float2 t1 = *(const float2*)&g_hn[(size_t)c0.y * HD + lane * 2];
        float2 t2 = *(const float2*)&g_hn[(size_t)c0.z * HD + lane * 2];
        float2 t3 = *(const float2*)&g_hn[(size_t)c0.w * HD + lane * 2];
        float2 t4 = *(const float2*)&g_hn[(size_t)c1.x * HD + lane * 2];
        float2 t5 = *(const float2*)&g_hn[(size_t)c1.y * HD + lane * 2];
        float2 t6 = *(const float2*)&g_hn[(size_t)c1.z * HD + lane * 2];
        float2 t7 = *(const float2*)&g_hn[(size_t)c1.w * HD + lane * 2];
        acc.x += ((t0.x + t1.x) + (t2.x + t3.x)) + ((t4.x + t5.x) + (t6.x + t7.x));
        acc.y += ((t0.y + t1.y) + (t2.y + t3.y)) + ((t4.y + t5.y) + (t6.y + t7.y));
    }
    if (p + 4 <= end) {
        int4 c0 = *(const int4*)&g_colidx[p];
        p += 4;
        float2 t0 = *(const float2*)&g_hn[(size_t)c0.x * HD + lane * 2];
        float2 t1 = *(const float2*)&g_hn[(size_t)c0.y * HD + lane * 2];
        float2 t2 = *(const float2*)&g_hn[(size_t)c0.z * HD + lane * 2];
        float2 t3 = *(const float2*)&g_hn[(size_t)c0.w * HD + lane * 2];
        acc.x += (t0.x + t1.x) + (t2.x + t3.x);
        acc.y += (t0.y + t1.y) + (t2.y + t3.y);
    }
    for (; p < end; p++) {
        int u = g_colidx[p];
        float2 t = *(const float2*)&g_hn[(size_t)u * HD + lane * 2];
        acc.x += t.x; acc.y += t.y;
    }
    return acc;
}

__global__ void k_agg(const float* __restrict__ bias, int first) {
    int warp = (blockIdx.x * blockDim.x + threadIdx.x) >> 5;
    int lane = threadIdx.x & 31;
    if (warp >= NN) return;
    int v = warp;

    float2 acc = warp_gather_sum(v, lane);
    float d = g_dis[v];
    float2 b = *(const float2*)&bias[lane * 2];
    float hx = fmaxf(fmaf(d, acc.x, b.x), 0.f);
    float hy = fmaxf(fmaf(d, acc.y, b.y), 0.f);

    size_t fo = (size_t)v * HD + lane * 2;
    *(float2*)&g_h[fo] = make_float2(hx, hy);
    if (first) {
        *(float2*)&g_jk[fo] = make_float2(hx, hy);
    } else {
        float2 j = *(const float2*)&g_jk[fo];
        *(float2*)&g_jk[fo] = make_float2(fmaxf(j.x, hx), fmaxf(j.y, hy));
    }
}

// Last layer: only jk update, no h store.
__global__ void k_agg_last(const float* __restrict__ bias) {
    int warp = (blockIdx.x * blockDim.x + threadIdx.x) >> 5;
    int lane = threadIdx.x & 31;
    if (warp >= NN) return;
    int v = warp;

    float2 acc = warp_gather_sum(v, lane);
    float d = g_dis[v];
    float2 b = *(const float2*)&bias[lane * 2];
    float hx = fmaxf(fmaf(d, acc.x, b.x), 0.f);
    float hy = fmaxf(fmaf(d, acc.y, b.y), 0.f);

    size_t fo = (size_t)v * HD + lane * 2;
    float2 j = *(const float2*)&g_jk[fo];
    *(float2*)&g_jk[fo] = make_float2(fmaxf(j.x, hx), fmaxf(j.y, hy));
}

// ---------------- head: warp per row, jk @ fc_w + fc_b, log_softmax ----------------
__global__ void k_proj(const float* __restrict__ fcw, const float* __restrict__ fcb,
                       float* __restrict__ out) {
    __shared__ float Wsm[HD * CC];
    __shared__ float bsm[CC];
    int tid = threadIdx.x;
    for (int i = tid; i < HD * CC; i += blockDim.x) Wsm[i] = fcw[i];
    if (tid < CC) bsm[tid] = fcb[tid];
    __syncthreads();

    int warp = (blockIdx.x * blockDim.x + tid) >> 5;
    int lane = tid & 31;
    if (warp >= NN) return;
    int v = warp;

    float2 jv = *(const float2*)&g_jk[(size_t)v * HD + lane * 2];
    bool act = lane < 20;                   // 20 lanes x 2 cols = 40
    int c0 = lane * 2;
    float a0 = 0.f, a1 = 0.f;
    #pragma unroll
    for (int k = 0; k < HD; k++) {
        float hv = __shfl_sync(0xffffffffu, (k & 1) ? jv.y : jv.x, k >> 1);
        if (act) {
            float2 w = *(const float2*)&Wsm[k * CC + c0];
            a0 = fmaf(hv, w.x, a0);
            a1 = fmaf(hv, w.y, a1);
        }
    }
    if (act) { a0 += bsm[c0]; a1 += bsm[c0 + 1]; }

    float m = act ? fmaxf(a0, a1) : -INFINITY;
    #pragma unroll
    for (int off = 16; off; off >>= 1) m = fmaxf(m, __shfl_xor_sync(0xffffffffu, m, off));
    float s = act ? (expf(a0 - m) + expf(a1 - m)) : 0.f;
    #pragma unroll
    for (int off = 16; off; off >>= 1) s += __shfl_xor_sync(0xffffffffu, s, off);
    float lse = m + logf(s);

    if (act) {
        float2 o = make_float2(a0 - lse, a1 - lse);
        *(float2*)&out[(size_t)v * CC + c0] = o;
    }
}

// ---------------- launch ----------------
extern "C" void kernel_launch(void* const* d_in, const int* in_sizes, int n_in,
                              void* d_out, int out_size) {
    const float* x   = (const float*)d_in[0];
    const int*   ei  = (const int*)  d_in[1];
    const float* W0  = (const float*)d_in[2];
    const float* Ws  = (const float*)d_in[3];
    const float* bs  = (const float*)d_in[4];
    const float* fcw = (const float*)d_in[5];
    const float* fcb = (const float*)d_in[6];
    float* out = (float*)d_out;

    const int* src = ei;         // edge_index[0]
    const int* dst = ei + EE;    // edge_index[1]

    // CSR build (once per call, reused by all 6 layers)
    k_zero_deg<<<(NN + 255) / 256, 256>>>();
    k_count   <<<(EE + 255) / 256, 256>>>(dst);
    k_scan    <<<1, 1024>>>();
    k_scatter <<<(EE + 255) / 256, 256>>>(src, dst);

    const int GEMM_GRID = (NN + 63) / 64;
    const int AGG_GRID  = (NN + 7) / 8;     // 8 warps per 256-thread block

    // layer 0: x (N x 128) @ W0
    k_gemm<FIN, true><<<GEMM_GRID, 256>>>(x, W0);
    k_agg<<<AGG_GRID, 256>>>(bs + 0 * HD, 1);

    // layers 1..4
    for (int l = 1; l < LL - 1; l++) {
        k_gemm<HD, false><<<GEMM_GRID, 256>>>(nullptr, Ws + (size_t)(l - 1) * HD * HD);
        k_agg<<<AGG_GRID, 256>>>(bs + (size_t)l * HD, 0);
    }
    // layer 5: no h store
    k_gemm<HD, false><<<GEMM_GRID, 256>>>(nullptr, Ws + (size_t)(LL - 2) * HD * HD);
    k_agg_last<<<AGG_GRID, 256>>>(bs + (size_t)(LL - 1) * HD);

    // head
    k_proj<<<AGG_GRID, 256>>>(fcw, fcb, out);
}